// round 11
// baseline (speedup 1.0000x reference)
#include <cuda_runtime.h>

#define BB 16
#define NN 256
#define FF 64
#define DD 128
#define HH 4
#define DHH 32
#define DFF_ 512
#define LL 2
#define ROWS (BB*NN)     // 4096
#define PP (NN*(NN-1))   // 65280
#define EPSF 1e-5f
#define SPLITS 4
#define BHQ (BB*HH*NN)   // 16384

// Wf segment offsets (floats)
#define WF_QKV   0
#define WF_QKV_L (16*48*128)          // 98304 per layer
#define WF_FFN1  (2*WF_QKV_L)         // 196608
#define WF_FFN1_L (16*64*128)         // 131072 per layer
#define WF_REL   (WF_FFN1 + 2*WF_FFN1_L)  // 458752
#define WF_TOTAL (WF_REL + 16*32*128)     // 524288

// ---------------- scratch ----------------
__device__ float g_x[ROWS*DD];
__device__ float g_qkv[ROWS*3*DD];    // qkv; reused for GEMM split-K partials
__device__ float g_ffn[ROWS*DFF_];    // ffn1 acts; also attention po scratch
__device__ float g_A[ROWS*DD];        // pairpre A; also attention l scratch
__device__ float g_Bm[ROWS*DD];
__device__ float g_Wf[WF_TOTAL];      // tf32 hi/lo weight fragments
__device__ float g_Xf[16*256*32*8];   // tf32 hi/lo X fragments [ks][rt][lane][8]

typedef unsigned long long u64;
typedef unsigned int u32;

__device__ __forceinline__ u64 pack2(float x, float y) {
  u64 r; asm("mov.b64 %0, {%1, %2};" : "=l"(r) : "f"(x), "f"(y)); return r;
}
__device__ __forceinline__ float2 unpack2(u64 v) {
  float2 r; asm("mov.b64 {%0, %1}, %2;" : "=f"(r.x), "=f"(r.y) : "l"(v)); return r;
}
__device__ __forceinline__ void ffma2(u64 &d, u64 a, u64 b) {
  asm("fma.rn.f32x2 %0, %1, %2, %0;" : "+l"(d) : "l"(a), "l"(b));
}
__device__ __forceinline__ u64 add2(u64 a, u64 b) {
  u64 o; asm("add.rn.f32x2 %0, %1, %2;" : "=l"(o) : "l"(a), "l"(b)); return o;
}
__device__ __forceinline__ u64 relu2(u64 v) {
  float2 f = unpack2(v);
  return pack2(fmaxf(f.x, 0.f), fmaxf(f.y, 0.f));
}
__device__ __forceinline__ u32 f2tf(float x) {
  u32 r; asm("cvt.rna.tf32.f32 %0, %1;" : "=r"(r) : "f"(x)); return r;
}
__device__ __forceinline__ void mma8(float& c0, float& c1, float& c2, float& c3,
                                     u32 a0, u32 a1, u32 a2, u32 a3, u32 b0, u32 b1) {
  asm volatile(
      "mma.sync.aligned.m16n8k8.row.col.f32.tf32.tf32.f32 "
      "{%0,%1,%2,%3}, {%4,%5,%6,%7}, {%8,%9}, {%0,%1,%2,%3};"
      : "+f"(c0), "+f"(c1), "+f"(c2), "+f"(c3)
      : "r"(a0), "r"(a1), "r"(a2), "r"(a3), "r"(b0), "r"(b1));
}

// ================ weight split: fp32 -> tf32 hi/lo fragments ================
// Segments: qkv (Z=2,K=128,N=384), ffn1 (Z=2,K=128,N=512), relw1 gather (K=128,N=256)
__global__ void __launch_bounds__(256) k_wsplit(const float* __restrict__ qkv_w,
                                                const float* __restrict__ ffn1_w,
                                                const float* __restrict__ rel_w1,
                                                float* __restrict__ Wf) {
  const int tid = blockIdx.x * 256 + threadIdx.x;  // 131072 total
  const float* src;
  int NT, N, local, dstoff, rel = 0;
  if (tid < 49152)        { src = qkv_w;  NT = 48; N = 384; local = tid;          dstoff = WF_QKV; }
  else if (tid < 114688)  { src = ffn1_w; NT = 64; N = 512; local = tid - 49152;  dstoff = WF_FFN1; }
  else                    { src = rel_w1; NT = 32; N = 256; local = tid - 114688; dstoff = WF_REL; rel = 1; }
  const int lane = local & 31;
  int u = local >> 5;
  const int nt = u % NT; u /= NT;
  const int ks = u & 15;
  const int z  = u >> 4;
  const int n = nt * 8 + (lane >> 2);
  float w[4];
  #pragma unroll
  for (int reg = 0; reg < 2; reg++) {
    const int kk = (lane & 3) + 4 * reg;
    const int k = ks * 8 + kk;
    float v;
    if (rel) v = src[(size_t)((n < 128) ? k : k + 128) * 128 + (n & 127)];
    else     v = src[(size_t)(z * 128 + k) * N + n];
    u32 hi = f2tf(v);
    float hf = __uint_as_float(hi);
    u32 lo = f2tf(v - hf);
    w[reg]     = hf;
    w[reg + 2] = __uint_as_float(lo);
  }
  *(float4*)&Wf[(size_t)dstoff + (size_t)(((z * 16 + ks) * NT + nt) * 32 + lane) * 4] =
      make_float4(w[0], w[1], w[2], w[3]);
}

// ================ tf32 MMA GEMM: warp tile 16x64, no smem ================
// EPI: 0 = +bias ; 1 = +bias,relu ; 5 = pairpre dual (blockIdx.y<2 -> Y(bias), else Y2)
template <int EPI>
__global__ void __launch_bounds__(128) k_tfmm(
    const float* __restrict__ Xf, const float* __restrict__ Wf,
    int NOUT, int NTILES,
    const float* __restrict__ bias,
    float* __restrict__ Y, float* __restrict__ Y2) {
  const int w = threadIdx.x >> 5, lane = threadIdx.x & 31;
  const int groupID = lane >> 2, tig = lane & 3;
  const int rt = blockIdx.x * 4 + w;
  const int ntg0 = blockIdx.y * 8;

  float acc[8][4];
  #pragma unroll
  for (int nt = 0; nt < 8; nt++) {
    float b0 = 0.f, b1 = 0.f;
    if (EPI != 5 || blockIdx.y < 2) {
      const int c = (ntg0 + nt) * 8 + tig * 2;
      b0 = bias[c]; b1 = bias[c + 1];
    }
    acc[nt][0] = b0; acc[nt][1] = b1; acc[nt][2] = b0; acc[nt][3] = b1;
  }

  const uint4* xfp = (const uint4*)(Xf + (size_t)(rt * 32 + lane) * 8);
  const uint4* wfp = (const uint4*)(Wf + (size_t)(ntg0 * 32 + lane) * 4);

  #pragma unroll 2
  for (int ks = 0; ks < 16; ks++) {
    // Xf ks-stride: 256 rt * 32 lanes * 8 floats = 65536 floats = 16384 uint4
    uint4 ah = xfp[(size_t)ks * 16384];
    uint4 al = xfp[(size_t)ks * 16384 + 1];
    #pragma unroll
    for (int nt = 0; nt < 8; nt++) {
      // Wf tile stride: 32 lanes * 4 floats = 128 floats = 32 uint4 per (ks,nt)
      uint4 b = wfp[(size_t)ks * NTILES * 32 + nt * 32];
      mma8(acc[nt][0], acc[nt][1], acc[nt][2], acc[nt][3],
           ah.x, ah.y, ah.z, ah.w, b.x, b.y);
      mma8(acc[nt][0], acc[nt][1], acc[nt][2], acc[nt][3],
           ah.x, ah.y, ah.z, ah.w, b.z, b.w);
      mma8(acc[nt][0], acc[nt][1], acc[nt][2], acc[nt][3],
           al.x, al.y, al.z, al.w, b.x, b.y);
    }
  }

  const int row0 = rt * 16 + groupID;
  #pragma unroll
  for (int nt = 0; nt < 8; nt++) {
    int colg = (ntg0 + nt) * 8 + tig * 2;
    float f0 = acc[nt][0], f1 = acc[nt][1], f2 = acc[nt][2], f3 = acc[nt][3];
    if (EPI == 1) {
      f0 = fmaxf(f0, 0.f); f1 = fmaxf(f1, 0.f);
      f2 = fmaxf(f2, 0.f); f3 = fmaxf(f3, 0.f);
    }
    if (EPI == 5) {
      float* Yo = (blockIdx.y < 2) ? Y : Y2;
      const int c = colg & 127;
      *(float2*)&Yo[(size_t)row0 * 128 + c]       = make_float2(f0, f1);
      *(float2*)&Yo[(size_t)(row0 + 8) * 128 + c] = make_float2(f2, f3);
    } else {
      *(float2*)&Y[(size_t)row0 * NOUT + colg]       = make_float2(f0, f1);
      *(float2*)&Y[(size_t)(row0 + 8) * NOUT + colg] = make_float2(f2, f3);
    }
  }
}

// ================ GEMM P: partial split-K, BM=32, BN=128, BK=16, 128 threads, 4x8 tile ================
template <int ATTN>
__global__ void __launch_bounds__(128) k_gemmP(
    const float* __restrict__ X,
    const float* __restrict__ po, const float* __restrict__ pl,
    int KK, int KH,
    const float* __restrict__ W,
    float* __restrict__ Yp) {
  __shared__ float As[2][16][32];
  __shared__ float Bs[2][16][128];
  const int t  = threadIdx.x;
  const int tx = t & 15, ty = t >> 4;
  const int bm0 = blockIdx.x * 32;
  const int z   = blockIdx.z;
  const int r0 = ty * 4, c0 = tx * 8;
  const int am = t >> 2,  akq = (t & 3) * 4;
  const int bkr = t >> 3, bcq = (t & 7) * 16;

  const int row = bm0 + am;
  const int kb  = z * KH + akq;

  int bq_b = 0, bq_q = 0;
  if (ATTN) { bq_b = row >> 8; bq_q = row & 255; }

  u64 acc[4][4];
  #pragma unroll
  for (int i = 0; i < 4; i++) { acc[i][0]=0; acc[i][1]=0; acc[i][2]=0; acc[i][3]=0; }

  const float* Xp = X + (size_t)row * KK + kb;
  const float* Wp = W + (size_t)(z * KH + bkr) * 128 + bcq;
  const int NT = KH >> 4;

  auto loadA = [&](int it) -> float4 {
    if (!ATTN) {
      return *(const float4*)(Xp + it * 16);
    } else {
      const int kk = kb + it * 16;
      const int h = kk >> 5, d4 = kk & 31;
      const int bhq = (bq_b * HH + h) * NN + bq_q;
      float lsum = pl[bhq] + pl[BHQ + bhq] + pl[2 * BHQ + bhq] + pl[3 * BHQ + bhq];
      float inv = 1.f / lsum;
      float4 p0 = *(const float4*)&po[((size_t)bhq) * 32 + d4];
      float4 p1 = *(const float4*)&po[((size_t)BHQ + bhq) * 32 + d4];
      float4 p2 = *(const float4*)&po[((size_t)2 * BHQ + bhq) * 32 + d4];
      float4 p3 = *(const float4*)&po[((size_t)3 * BHQ + bhq) * 32 + d4];
      return make_float4((p0.x + p1.x + p2.x + p3.x) * inv,
                         (p0.y + p1.y + p2.y + p3.y) * inv,
                         (p0.z + p1.z + p2.z + p3.z) * inv,
                         (p0.w + p1.w + p2.w + p3.w) * inv);
    }
  };

  float4 a0 = loadA(0);
  float4 b0 = *(const float4*)Wp;
  float4 b1 = *(const float4*)(Wp + 4);
  float4 b2 = *(const float4*)(Wp + 8);
  float4 b3 = *(const float4*)(Wp + 12);
  {
    As[0][akq + 0][am] = a0.x; As[0][akq + 1][am] = a0.y;
    As[0][akq + 2][am] = a0.z; As[0][akq + 3][am] = a0.w;
    *(float4*)&Bs[0][bkr][bcq]      = b0;
    *(float4*)&Bs[0][bkr][bcq + 4]  = b1;
    *(float4*)&Bs[0][bkr][bcq + 8]  = b2;
    *(float4*)&Bs[0][bkr][bcq + 12] = b3;
  }
  __syncthreads();

  for (int it = 0; it < NT; it++) {
    const int buf = it & 1;
    if (it + 1 < NT) {
      a0 = loadA(it + 1);
      const float* wp = Wp + (size_t)(it + 1) * 16 * 128;
      b0 = *(const float4*)wp;        b1 = *(const float4*)(wp + 4);
      b2 = *(const float4*)(wp + 8);  b3 = *(const float4*)(wp + 12);
    }
    #pragma unroll
    for (int k = 0; k < 16; k++) {
      float4 av = *(const float4*)&As[buf][k][r0];
      ulonglong2 bv0 = *(const ulonglong2*)&Bs[buf][k][c0];
      ulonglong2 bv1 = *(const ulonglong2*)&Bs[buf][k][c0 + 4];
      u64 pa0 = pack2(av.x, av.x);
      u64 pa1 = pack2(av.y, av.y);
      u64 pa2 = pack2(av.z, av.z);
      u64 pa3 = pack2(av.w, av.w);
      ffma2(acc[0][0], pa0, bv0.x); ffma2(acc[0][1], pa0, bv0.y);
      ffma2(acc[0][2], pa0, bv1.x); ffma2(acc[0][3], pa0, bv1.y);
      ffma2(acc[1][0], pa1, bv0.x); ffma2(acc[1][1], pa1, bv0.y);
      ffma2(acc[1][2], pa1, bv1.x); ffma2(acc[1][3], pa1, bv1.y);
      ffma2(acc[2][0], pa2, bv0.x); ffma2(acc[2][1], pa2, bv0.y);
      ffma2(acc[2][2], pa2, bv1.x); ffma2(acc[2][3], pa2, bv1.y);
      ffma2(acc[3][0], pa3, bv0.x); ffma2(acc[3][1], pa3, bv0.y);
      ffma2(acc[3][2], pa3, bv1.x); ffma2(acc[3][3], pa3, bv1.y);
    }
    if (it + 1 < NT) {
      const int nb = buf ^ 1;
      As[nb][akq + 0][am] = a0.x; As[nb][akq + 1][am] = a0.y;
      As[nb][akq + 2][am] = a0.z; As[nb][akq + 3][am] = a0.w;
      *(float4*)&Bs[nb][bkr][bcq]      = b0;
      *(float4*)&Bs[nb][bkr][bcq + 4]  = b1;
      *(float4*)&Bs[nb][bkr][bcq + 8]  = b2;
      *(float4*)&Bs[nb][bkr][bcq + 12] = b3;
    }
    __syncthreads();
  }

  float* yp = Yp + (size_t)z * (ROWS * DD) + (size_t)(bm0 + r0) * DD + c0;
  #pragma unroll
  for (int i = 0; i < 4; i++) {
    float2 u0 = unpack2(acc[i][0]), u1 = unpack2(acc[i][1]);
    float2 u2 = unpack2(acc[i][2]), u3 = unpack2(acc[i][3]);
    *(float4*)(yp + (size_t)i * DD)     = make_float4(u0.x, u0.y, u1.x, u1.y);
    *(float4*)(yp + (size_t)i * DD + 4) = make_float4(u2.x, u2.y, u3.x, u3.y);
  }
}

// ================ combine + bias (+relu|+res) + LayerNorm + write tf32 X fragments ================
template <int RELU, int RES, int TWO>
__global__ void __launch_bounds__(256) k_combln(
    const float* __restrict__ p0, const float* __restrict__ p1,
    const float* __restrict__ bias, const float* __restrict__ res,
    const float* __restrict__ g, const float* __restrict__ beta,
    float* __restrict__ Y, float* __restrict__ Xf) {
  const int row = blockIdx.x * 8 + (threadIdx.x >> 5);
  const int lane = threadIdx.x & 31;
  const int c0 = lane * 4;
  const size_t off = (size_t)row * DD + c0;

  float4 v = *(const float4*)&p0[off];
  if (TWO) {
    float4 w = *(const float4*)&p1[off];
    v.x += w.x; v.y += w.y; v.z += w.z; v.w += w.w;
  }
  float4 bv = *(const float4*)&bias[c0];
  v.x += bv.x; v.y += bv.y; v.z += bv.z; v.w += bv.w;
  if (RELU) {
    v.x = fmaxf(v.x, 0.f); v.y = fmaxf(v.y, 0.f);
    v.z = fmaxf(v.z, 0.f); v.w = fmaxf(v.w, 0.f);
  }
  if (RES) {
    float4 r = *(const float4*)&res[off];
    v.x += r.x; v.y += r.y; v.z += r.z; v.w += r.w;
  }
  float s  = v.x + v.y + v.z + v.w;
  float s2 = v.x * v.x + v.y * v.y + v.z * v.z + v.w * v.w;
  #pragma unroll
  for (int o = 16; o; o >>= 1) {
    s  += __shfl_xor_sync(0xffffffffu, s,  o);
    s2 += __shfl_xor_sync(0xffffffffu, s2, o);
  }
  float mu = s * (1.f / 128.f);
  float var = s2 * (1.f / 128.f) - mu * mu;
  float rstd = rsqrtf(var + EPSF);
  float4 gv = *(const float4*)&g[c0];
  float4 ev = *(const float4*)&beta[c0];
  float o0 = (v.x - mu) * rstd * gv.x + ev.x;
  float o1 = (v.y - mu) * rstd * gv.y + ev.y;
  float o2 = (v.z - mu) * rstd * gv.z + ev.z;
  float o3 = (v.w - mu) * rstd * gv.w + ev.w;
  *(float4*)&Y[off] = make_float4(o0, o1, o2, o3);

  // write tf32 hi/lo fragments: Xf[ks][rt][lane_f][8]
  const int rt = row >> 4, r = row & 15;
  float ov[4] = {o0, o1, o2, o3};
  #pragma unroll
  for (int j = 0; j < 4; j++) {
    const int k = c0 + j;
    const int ks = k >> 3, kk = k & 7;
    const int lane_f = ((r & 7) << 2) | (kk & 3);
    const int reg = (r >> 3) | ((kk >> 2) << 1);
    const size_t idx = (size_t)((ks << 8) | rt) * 256 + lane_f * 8 + reg;
    u32 hi = f2tf(ov[j]);
    float hf = __uint_as_float(hi);
    Xf[idx]     = hf;
    Xf[idx + 4] = __uint_as_float(f2tf(ov[j] - hf));
  }
}

// ================ attention: branch-free split-K partials, 2 queries per thread ================
__global__ void __launch_bounds__(128) k_attn_part(const float* __restrict__ qkv,
                                                   float* __restrict__ po,
                                                   float* __restrict__ pl) {
  const int split = blockIdx.x, h = blockIdx.y, b = blockIdx.z;
  const int t = threadIdx.x;  // 128
  const int q0 = t, q1 = t + 128;
  __shared__ float Ks[64][DHH], Vs[64][DHH];
  const float* base = qkv + (size_t)b * NN * (3 * DD);
  const int hoff = h * DHH;
  const int kbase = split * 64;

  for (int c = t; c < 64 * DHH / 4; c += 128) {
    int r = c >> 3, d4 = (c & 7) << 2;
    *(float4*)&Ks[r][d4] = *(const float4*)&base[(size_t)(kbase + r) * (3 * DD) + DD     + hoff + d4];
    *(float4*)&Vs[r][d4] = *(const float4*)&base[(size_t)(kbase + r) * (3 * DD) + 2 * DD + hoff + d4];
  }
  u64 qp0[16], qp1[16];
  {
    const ulonglong2* qa = (const ulonglong2*)(base + (size_t)q0 * (3 * DD) + hoff);
    const ulonglong2* qb = (const ulonglong2*)(base + (size_t)q1 * (3 * DD) + hoff);
    #pragma unroll
    for (int i = 0; i < 8; i++) {
      ulonglong2 u = qa[i]; qp0[2*i] = u.x; qp0[2*i+1] = u.y;
      ulonglong2 v = qb[i]; qp1[2*i] = v.x; qp1[2*i+1] = v.y;
    }
  }
  __syncthreads();

  float l0 = 0.f, l1 = 0.f;
  u64 op0[16], op1[16];
  #pragma unroll
  for (int i = 0; i < 16; i++) { op0[i] = 0ull; op1[i] = 0ull; }
  const float scale = 0.17677669529663687f;

  for (int k = 0; k < 64; k++) {
    const ulonglong2* kr = (const ulonglong2*)&Ks[k][0];
    u64 sa0 = 0, sa1 = 0, sa2 = 0, sa3 = 0;
    u64 sb0 = 0, sb1 = 0, sb2 = 0, sb3 = 0;
    #pragma unroll
    for (int i = 0; i < 4; i++) {
      ulonglong2 ka = kr[2*i], kb = kr[2*i+1];
      ffma2(sa0, qp0[4*i],     ka.x);
      ffma2(sa1, qp0[4*i + 1], ka.y);
      ffma2(sa2, qp0[4*i + 2], kb.x);
      ffma2(sa3, qp0[4*i + 3], kb.y);
      ffma2(sb0, qp1[4*i],     ka.x);
      ffma2(sb1, qp1[4*i + 1], ka.y);
      ffma2(sb2, qp1[4*i + 2], kb.x);
      ffma2(sb3, qp1[4*i + 3], kb.y);
    }
    u64 ra = add2(add2(sa0, sa1), add2(sa2, sa3));
    u64 rb = add2(add2(sb0, sb1), add2(sb2, sb3));
    float2 ua = unpack2(ra), ub = unpack2(rb);
    float p0 = __expf((ua.x + ua.y) * scale);
    float p1 = __expf((ub.x + ub.y) * scale);
    l0 += p0;
    l1 += p1;
    u64 pp0 = pack2(p0, p0), pp1 = pack2(p1, p1);
    const ulonglong2* vr = (const ulonglong2*)&Vs[k][0];
    #pragma unroll
    for (int i = 0; i < 8; i++) {
      ulonglong2 vv = vr[i];
      ffma2(op0[2*i],     pp0, vv.x);
      ffma2(op0[2*i + 1], pp0, vv.y);
      ffma2(op1[2*i],     pp1, vv.x);
      ffma2(op1[2*i + 1], pp1, vv.y);
    }
  }

  const int bh = (b * HH + h) * NN;
  {
    const int bhq = bh + q0;
    float* pop = po + ((size_t)split * BHQ + bhq) * 32;
    #pragma unroll
    for (int i = 0; i < 8; i++) {
      float2 a = unpack2(op0[2*i]), c = unpack2(op0[2*i + 1]);
      *(float4*)&pop[4*i] = make_float4(a.x, a.y, c.x, c.y);
    }
    pl[(size_t)split * BHQ + bhq] = l0;
  }
  {
    const int bhq = bh + q1;
    float* pop = po + ((size_t)split * BHQ + bhq) * 32;
    #pragma unroll
    for (int i = 0; i < 8; i++) {
      float2 a = unpack2(op1[2*i]), c = unpack2(op1[2*i + 1]);
      *(float4*)&pop[4*i] = make_float4(a.x, a.y, c.x, c.y);
    }
    pl[(size_t)split * BHQ + bhq] = l1;
  }
}

// ================ pair kernel: 64i x 64j per block, 4x4 pairs per thread ================
#define SP 132
__global__ void __launch_bounds__(256) k_pair(const float* __restrict__ w2,
                                              const float* __restrict__ b2,
                                              float* __restrict__ out) {
  extern __shared__ float sm[];
  float* smA = sm;
  float* smB = sm + 64 * SP;
  float* smw = sm + 128 * SP;
  const int b  = blockIdx.z;
  const int i0 = blockIdx.x * 64;
  const int j0 = blockIdx.y * 64;
  const int t  = threadIdx.x;
  const int jx = t & 15, iy = t >> 4;

  {
    const float* Ab = g_A  + ((size_t)(b * NN + i0)) * DD;
    const float* Bb = g_Bm + ((size_t)(b * NN + j0)) * DD;
    for (int idx = t; idx < 64 * 32; idx += 256) {
      int r = idx >> 5, dq = (idx & 31) << 2;
      *(float4*)&smA[r * SP + dq] = *(const float4*)&Ab[(size_t)r * DD + dq];
      *(float4*)&smB[r * SP + dq] = *(const float4*)&Bb[(size_t)r * DD + dq];
    }
    if (t < 32) *(float4*)&smw[t * 4] = *(const float4*)&w2[t * 4];
  }
  __syncthreads();

  const int ibl = iy * 4;
  u64 acc[4][4];
  #pragma unroll
  for (int ii = 0; ii < 4; ii++)
    #pragma unroll
    for (int jj = 0; jj < 4; jj++) acc[ii][jj] = 0ull;

  for (int d = 0; d < DD; d += 4) {
    ulonglong2 wv = *(const ulonglong2*)&smw[d];
    ulonglong2 av[4], bv[4];
    #pragma unroll
    for (int ii = 0; ii < 4; ii++) av[ii] = *(const ulonglong2*)&smA[(ibl + ii) * SP + d];
    #pragma unroll
    for (int jj = 0; jj < 4; jj++) bv[jj] = *(const ulonglong2*)&smB[(jx + 16 * jj) * SP + d];
    #pragma unroll
    for (int ii = 0; ii < 4; ii++) {
      #pragma unroll
      for (int jj = 0; jj < 4; jj++) {
        u64 s0 = relu2(add2(av[ii].x, bv[jj].x));
        ffma2(acc[ii][jj], s0, wv.x);
        u64 s1 = relu2(add2(av[ii].y, bv[jj].y));
        ffma2(acc[ii][jj], s1, wv.y);
      }
    }
  }

  const float b2v = b2[0];
  float* outb = out + (size_t)b * PP;
  #pragma unroll
  for (int ii = 0; ii < 4; ii++) {
    const int i = i0 + ibl + ii;
    #pragma unroll
    for (int jj = 0; jj < 4; jj++) {
      const int j = j0 + jx + 16 * jj;
      if (j != i) {
        float2 u = unpack2(acc[ii][jj]);
        outb[i * (NN - 1) + j - (j > i ? 1 : 0)] = u.x + u.y + b2v;
      }
    }
  }
}

// ================ host ================
extern "C" void kernel_launch(void* const* d_in, const int* in_sizes, int n_in,
                              void* d_out, int out_size) {
  const float* agents   = (const float*)d_in[0];
  const float* enc_w    = (const float*)d_in[1];
  const float* enc_b    = (const float*)d_in[2];
  const float* enc_g    = (const float*)d_in[3];
  const float* enc_beta = (const float*)d_in[4];
  const float* qkv_w    = (const float*)d_in[5];
  const float* qkv_b    = (const float*)d_in[6];
  const float* attn_ow  = (const float*)d_in[7];
  const float* attn_ob  = (const float*)d_in[8];
  const float* ln1_g    = (const float*)d_in[9];
  const float* ln1_b    = (const float*)d_in[10];
  const float* ffn_w1   = (const float*)d_in[11];
  const float* ffn_b1   = (const float*)d_in[12];
  const float* ffn_w2   = (const float*)d_in[13];
  const float* ffn_b2   = (const float*)d_in[14];
  const float* ln2_g    = (const float*)d_in[15];
  const float* ln2_b    = (const float*)d_in[16];
  const float* rel_w1   = (const float*)d_in[17];
  const float* rel_b1   = (const float*)d_in[18];
  const float* rel_w2   = (const float*)d_in[19];
  const float* rel_b2   = (const float*)d_in[20];
  float* out = (float*)d_out;

  float *px, *pqkv, *pffn, *pA, *pBm, *pWf, *pXf;
  cudaGetSymbolAddress((void**)&px,    g_x);
  cudaGetSymbolAddress((void**)&pqkv,  g_qkv);
  cudaGetSymbolAddress((void**)&pffn,  g_ffn);
  cudaGetSymbolAddress((void**)&pA,    g_A);
  cudaGetSymbolAddress((void**)&pBm,   g_Bm);
  cudaGetSymbolAddress((void**)&pWf,   g_Wf);
  cudaGetSymbolAddress((void**)&pXf,   g_Xf);
  float* ppart = pqkv;             // split-K partials
  float* ppo   = pffn;             // attention partial outputs
  float* ppl   = pA;               // attention partial l sums

  const int pair_smem = (128 * SP + 128) * sizeof(float);
  cudaFuncSetAttribute(k_pair, cudaFuncAttributeMaxDynamicSharedMemorySize, pair_smem);

  // weight fragment split (all weights, one launch)
  k_wsplit<<<512, 256>>>(qkv_w, ffn_w1, rel_w1, pWf);

  // encoder: relu(agents @ enc_w + b) -> LN (writes x and Xf)
  k_gemmP<0><<<dim3(ROWS / 32, 1, 1), 128>>>(agents, nullptr, nullptr, FF, FF,
                                             enc_w, ppart);
  k_combln<1, 0, 0><<<ROWS / 8, 256>>>(ppart, nullptr, enc_b, nullptr,
                                       enc_g, enc_beta, px, pXf);

  for (int l = 0; l < LL; l++) {
    // qkv via tf32 MMA
    k_tfmm<0><<<dim3(ROWS / 64, 6), 128>>>(pXf, pWf + WF_QKV + (size_t)l * WF_QKV_L,
                                           3 * DD, 48, qkv_b + (size_t)l * 3 * DD,
                                           pqkv, nullptr);
    // attention partials
    k_attn_part<<<dim3(SPLITS, HH, BB), 128>>>(pqkv, ppo, ppl);
    // proj (attention combine fused), split-K x2
    k_gemmP<1><<<dim3(ROWS / 32, 1, 2), 128>>>(nullptr, ppo, ppl, DD, DD / 2,
                                               attn_ow + (size_t)l * DD * DD, ppart);
    k_combln<0, 1, 1><<<ROWS / 8, 256>>>(ppart, ppart + (size_t)ROWS * DD,
                                         attn_ob + (size_t)l * DD, px,
                                         ln1_g + (size_t)l * DD, ln1_b + (size_t)l * DD,
                                         px, pXf);
    // ffn1 via tf32 MMA
    k_tfmm<1><<<dim3(ROWS / 64, 8), 128>>>(pXf, pWf + WF_FFN1 + (size_t)l * WF_FFN1_L,
                                           DFF_, 64, ffn_b1 + (size_t)l * DFF_,
                                           pffn, nullptr);
    // ffn2 split-K x2
    k_gemmP<0><<<dim3(ROWS / 32, 1, 2), 128>>>(pffn, nullptr, nullptr, DFF_, DFF_ / 2,
                                               ffn_w2 + (size_t)l * DFF_ * DD, ppart);
    k_combln<0, 1, 1><<<ROWS / 8, 256>>>(ppart, ppart + (size_t)ROWS * DD,
                                         ffn_b2 + (size_t)l * DD, px,
                                         ln2_g + (size_t)l * DD, ln2_b + (size_t)l * DD,
                                         px, pXf);
  }

  // pair precompute via tf32 MMA (dual output)
  k_tfmm<5><<<dim3(ROWS / 64, 4), 128>>>(pXf, pWf + WF_REL, DD, 32, rel_b1, pA, pBm);

  k_pair<<<dim3(NN / 64, NN / 64, BB), 256, pair_smem>>>(rel_w2, rel_b2, out);
}

// round 12
// speedup vs baseline: 1.0963x; 1.0963x over previous
#include <cuda_runtime.h>

#define BB 16
#define NN 256
#define FF 64
#define DD 128
#define HH 4
#define DHH 32
#define DFF_ 512
#define LL 2
#define ROWS (BB*NN)     // 4096
#define PP (NN*(NN-1))   // 65280
#define EPSF 1e-5f
#define SPLITS 4
#define BHQ (BB*HH*NN)   // 16384

// Wf segment offsets (floats)
#define WF_QKV   0
#define WF_QKV_L (16*48*128)          // 98304 per layer
#define WF_FFN1  (2*WF_QKV_L)         // 196608
#define WF_FFN1_L (16*64*128)         // 131072 per layer
#define WF_REL   (WF_FFN1 + 2*WF_FFN1_L)  // 458752
#define WF_TOTAL (WF_REL + 16*32*128)     // 524288

// ---------------- scratch ----------------
__device__ float g_x[ROWS*DD];
__device__ float g_qkv[ROWS*3*DD];    // qkv; reused for GEMM split-K partials
__device__ float g_ffn[ROWS*DFF_];    // ffn1 acts; also attention po scratch
__device__ float g_A[ROWS*DD];        // pairpre A; also attention l scratch
__device__ float g_Bm[ROWS*DD];
__device__ float g_Wf[WF_TOTAL];      // tf32 hi/lo weight fragments
__device__ float g_Xf[16*256*32*8];   // tf32 hi/lo X fragments [ks][rt][lane][8]

typedef unsigned long long u64;
typedef unsigned int u32;

__device__ __forceinline__ u64 pack2(float x, float y) {
  u64 r; asm("mov.b64 %0, {%1, %2};" : "=l"(r) : "f"(x), "f"(y)); return r;
}
__device__ __forceinline__ float2 unpack2(u64 v) {
  float2 r; asm("mov.b64 {%0, %1}, %2;" : "=f"(r.x), "=f"(r.y) : "l"(v)); return r;
}
__device__ __forceinline__ void ffma2(u64 &d, u64 a, u64 b) {
  asm("fma.rn.f32x2 %0, %1, %2, %0;" : "+l"(d) : "l"(a), "l"(b));
}
__device__ __forceinline__ u64 add2(u64 a, u64 b) {
  u64 o; asm("add.rn.f32x2 %0, %1, %2;" : "=l"(o) : "l"(a), "l"(b)); return o;
}
__device__ __forceinline__ u64 relu2(u64 v) {
  float2 f = unpack2(v);
  return pack2(fmaxf(f.x, 0.f), fmaxf(f.y, 0.f));
}
__device__ __forceinline__ u32 f2tf(float x) {
  u32 r; asm("cvt.rna.tf32.f32 %0, %1;" : "=r"(r) : "f"(x)); return r;
}
__device__ __forceinline__ void mma8(float& c0, float& c1, float& c2, float& c3,
                                     u32 a0, u32 a1, u32 a2, u32 a3, u32 b0, u32 b1) {
  asm volatile(
      "mma.sync.aligned.m16n8k8.row.col.f32.tf32.tf32.f32 "
      "{%0,%1,%2,%3}, {%4,%5,%6,%7}, {%8,%9}, {%0,%1,%2,%3};"
      : "+f"(c0), "+f"(c1), "+f"(c2), "+f"(c3)
      : "r"(a0), "r"(a1), "r"(a2), "r"(a3), "r"(b0), "r"(b1));
}

// ================ weight split: fp32 -> tf32 hi/lo fragments ================
__global__ void __launch_bounds__(256) k_wsplit(const float* __restrict__ qkv_w,
                                                const float* __restrict__ ffn1_w,
                                                const float* __restrict__ rel_w1,
                                                float* __restrict__ Wf) {
  const int tid = blockIdx.x * 256 + threadIdx.x;  // 131072 total
  const float* src;
  int NT, N, local, dstoff, rel = 0;
  if (tid < 49152)        { src = qkv_w;  NT = 48; N = 384; local = tid;          dstoff = WF_QKV; }
  else if (tid < 114688)  { src = ffn1_w; NT = 64; N = 512; local = tid - 49152;  dstoff = WF_FFN1; }
  else                    { src = rel_w1; NT = 32; N = 256; local = tid - 114688; dstoff = WF_REL; rel = 1; }
  const int lane = local & 31;
  int u = local >> 5;
  const int nt = u % NT; u /= NT;
  const int ks = u & 15;
  const int z  = u >> 4;
  const int n = nt * 8 + (lane >> 2);
  float w[4];
  #pragma unroll
  for (int reg = 0; reg < 2; reg++) {
    const int kk = (lane & 3) + 4 * reg;
    const int k = ks * 8 + kk;
    float v;
    if (rel) v = src[(size_t)((n < 128) ? k : k + 128) * 128 + (n & 127)];
    else     v = src[(size_t)(z * 128 + k) * N + n];
    u32 hi = f2tf(v);
    float hf = __uint_as_float(hi);
    u32 lo = f2tf(v - hf);
    w[reg]     = hf;
    w[reg + 2] = __uint_as_float(lo);
  }
  *(float4*)&Wf[(size_t)dstoff + (size_t)(((z * 16 + ks) * NT + nt) * 32 + lane) * 4] =
      make_float4(w[0], w[1], w[2], w[3]);
}

// ================ tf32 MMA GEMM v2: smem-staged W, double-buffered, prefetched ================
// Block: 128 threads (4 warps). Warp tile 16x64. All warps share the 8 W tiles per ks.
// EPI: 0 = +bias ; 1 = +bias,relu ; 5 = pairpre dual (blockIdx.y<2 -> Y(bias), else Y2)
template <int EPI>
__global__ void __launch_bounds__(128) k_tfmm(
    const float* __restrict__ Xf, const float* __restrict__ Wf,
    int NOUT, int NTILES,
    const float* __restrict__ bias,
    float* __restrict__ Y, float* __restrict__ Y2) {
  __shared__ float Ws[2][1024];      // 8 nt tiles x 128 floats, double buffered
  const int t = threadIdx.x;
  const int w = t >> 5, lane = t & 31;
  const int groupID = lane >> 5 ? 0 : (lane >> 2);  // lane>>2
  const int gid = lane >> 2, tig = lane & 3;
  const int rt = blockIdx.x * 4 + w;
  const int ntg0 = blockIdx.y * 8;

  float acc[8][4];
  #pragma unroll
  for (int nt = 0; nt < 8; nt++) {
    float b0 = 0.f, b1 = 0.f;
    if (EPI != 5 || blockIdx.y < 2) {
      const int c = (ntg0 + nt) * 8 + tig * 2;
      b0 = bias[c]; b1 = bias[c + 1];
    }
    acc[nt][0] = b0; acc[nt][1] = b1; acc[nt][2] = b0; acc[nt][3] = b1;
  }

  // Global pointers.
  // W: per-ks tile-group of 1024 contiguous floats at (ks*NTILES + ntg0)*128
  const float4* wgp = (const float4*)(Wf + (size_t)ntg0 * 128);  // + ks*NTILES*32 (float4)
  const uint4*  xfp = (const uint4*)(Xf + (size_t)(rt * 32 + lane) * 8);  // + ks*16384 (uint4)

  // Preload ks = 0
  float4 cw0 = wgp[t], cw1 = wgp[t + 128];
  uint4 ah = xfp[0], al = xfp[1];
  *(float4*)&Ws[0][t * 4]         = cw0;
  *(float4*)&Ws[0][(t + 128) * 4] = cw1;
  __syncthreads();

  int buf = 0;
  for (int ks = 0; ks < 16; ks++) {
    float4 nw0, nw1;
    uint4 nah, nal;
    if (ks + 1 < 16) {
      const size_t wo = (size_t)(ks + 1) * NTILES * 32;
      nw0 = wgp[wo + t];
      nw1 = wgp[wo + t + 128];
      nah = xfp[(size_t)(ks + 1) * 16384];
      nal = xfp[(size_t)(ks + 1) * 16384 + 1];
    }
    #pragma unroll
    for (int nt = 0; nt < 8; nt++) {
      uint4 b = *(const uint4*)&Ws[buf][nt * 128 + lane * 4];
      mma8(acc[nt][0], acc[nt][1], acc[nt][2], acc[nt][3],
           ah.x, ah.y, ah.z, ah.w, b.x, b.y);
      mma8(acc[nt][0], acc[nt][1], acc[nt][2], acc[nt][3],
           ah.x, ah.y, ah.z, ah.w, b.z, b.w);
      mma8(acc[nt][0], acc[nt][1], acc[nt][2], acc[nt][3],
           al.x, al.y, al.z, al.w, b.x, b.y);
    }
    if (ks + 1 < 16) {
      const int nb = buf ^ 1;
      *(float4*)&Ws[nb][t * 4]         = nw0;
      *(float4*)&Ws[nb][(t + 128) * 4] = nw1;
      ah = nah; al = nal;
      __syncthreads();
      buf = nb;
    }
  }

  const int row0 = rt * 16 + gid;
  #pragma unroll
  for (int nt = 0; nt < 8; nt++) {
    int colg = (ntg0 + nt) * 8 + tig * 2;
    float f0 = acc[nt][0], f1 = acc[nt][1], f2 = acc[nt][2], f3 = acc[nt][3];
    if (EPI == 1) {
      f0 = fmaxf(f0, 0.f); f1 = fmaxf(f1, 0.f);
      f2 = fmaxf(f2, 0.f); f3 = fmaxf(f3, 0.f);
    }
    if (EPI == 5) {
      float* Yo = (blockIdx.y < 2) ? Y : Y2;
      const int c = colg & 127;
      *(float2*)&Yo[(size_t)row0 * 128 + c]       = make_float2(f0, f1);
      *(float2*)&Yo[(size_t)(row0 + 8) * 128 + c] = make_float2(f2, f3);
    } else {
      *(float2*)&Y[(size_t)row0 * NOUT + colg]       = make_float2(f0, f1);
      *(float2*)&Y[(size_t)(row0 + 8) * NOUT + colg] = make_float2(f2, f3);
    }
  }
}

// ================ GEMM P: partial split-K, BM=32, BN=128, BK=16, 128 threads, 4x8 tile ================
template <int ATTN>
__global__ void __launch_bounds__(128) k_gemmP(
    const float* __restrict__ X,
    const float* __restrict__ po, const float* __restrict__ pl,
    int KK, int KH,
    const float* __restrict__ W,
    float* __restrict__ Yp) {
  __shared__ float As[2][16][32];
  __shared__ float Bs[2][16][128];
  const int t  = threadIdx.x;
  const int tx = t & 15, ty = t >> 4;
  const int bm0 = blockIdx.x * 32;
  const int z   = blockIdx.z;
  const int r0 = ty * 4, c0 = tx * 8;
  const int am = t >> 2,  akq = (t & 3) * 4;
  const int bkr = t >> 3, bcq = (t & 7) * 16;

  const int row = bm0 + am;
  const int kb  = z * KH + akq;

  int bq_b = 0, bq_q = 0;
  if (ATTN) { bq_b = row >> 8; bq_q = row & 255; }

  u64 acc[4][4];
  #pragma unroll
  for (int i = 0; i < 4; i++) { acc[i][0]=0; acc[i][1]=0; acc[i][2]=0; acc[i][3]=0; }

  const float* Xp = X + (size_t)row * KK + kb;
  const float* Wp = W + (size_t)(z * KH + bkr) * 128 + bcq;
  const int NT = KH >> 4;

  auto loadA = [&](int it) -> float4 {
    if (!ATTN) {
      return *(const float4*)(Xp + it * 16);
    } else {
      const int kk = kb + it * 16;
      const int h = kk >> 5, d4 = kk & 31;
      const int bhq = (bq_b * HH + h) * NN + bq_q;
      float lsum = pl[bhq] + pl[BHQ + bhq] + pl[2 * BHQ + bhq] + pl[3 * BHQ + bhq];
      float inv = 1.f / lsum;
      float4 p0 = *(const float4*)&po[((size_t)bhq) * 32 + d4];
      float4 p1 = *(const float4*)&po[((size_t)BHQ + bhq) * 32 + d4];
      float4 p2 = *(const float4*)&po[((size_t)2 * BHQ + bhq) * 32 + d4];
      float4 p3 = *(const float4*)&po[((size_t)3 * BHQ + bhq) * 32 + d4];
      return make_float4((p0.x + p1.x + p2.x + p3.x) * inv,
                         (p0.y + p1.y + p2.y + p3.y) * inv,
                         (p0.z + p1.z + p2.z + p3.z) * inv,
                         (p0.w + p1.w + p2.w + p3.w) * inv);
    }
  };

  float4 a0 = loadA(0);
  float4 b0 = *(const float4*)Wp;
  float4 b1 = *(const float4*)(Wp + 4);
  float4 b2 = *(const float4*)(Wp + 8);
  float4 b3 = *(const float4*)(Wp + 12);
  {
    As[0][akq + 0][am] = a0.x; As[0][akq + 1][am] = a0.y;
    As[0][akq + 2][am] = a0.z; As[0][akq + 3][am] = a0.w;
    *(float4*)&Bs[0][bkr][bcq]      = b0;
    *(float4*)&Bs[0][bkr][bcq + 4]  = b1;
    *(float4*)&Bs[0][bkr][bcq + 8]  = b2;
    *(float4*)&Bs[0][bkr][bcq + 12] = b3;
  }
  __syncthreads();

  for (int it = 0; it < NT; it++) {
    const int buf = it & 1;
    if (it + 1 < NT) {
      a0 = loadA(it + 1);
      const float* wp = Wp + (size_t)(it + 1) * 16 * 128;
      b0 = *(const float4*)wp;        b1 = *(const float4*)(wp + 4);
      b2 = *(const float4*)(wp + 8);  b3 = *(const float4*)(wp + 12);
    }
    #pragma unroll
    for (int k = 0; k < 16; k++) {
      float4 av = *(const float4*)&As[buf][k][r0];
      ulonglong2 bv0 = *(const ulonglong2*)&Bs[buf][k][c0];
      ulonglong2 bv1 = *(const ulonglong2*)&Bs[buf][k][c0 + 4];
      u64 pa0 = pack2(av.x, av.x);
      u64 pa1 = pack2(av.y, av.y);
      u64 pa2 = pack2(av.z, av.z);
      u64 pa3 = pack2(av.w, av.w);
      ffma2(acc[0][0], pa0, bv0.x); ffma2(acc[0][1], pa0, bv0.y);
      ffma2(acc[0][2], pa0, bv1.x); ffma2(acc[0][3], pa0, bv1.y);
      ffma2(acc[1][0], pa1, bv0.x); ffma2(acc[1][1], pa1, bv0.y);
      ffma2(acc[1][2], pa1, bv1.x); ffma2(acc[1][3], pa1, bv1.y);
      ffma2(acc[2][0], pa2, bv0.x); ffma2(acc[2][1], pa2, bv0.y);
      ffma2(acc[2][2], pa2, bv1.x); ffma2(acc[2][3], pa2, bv1.y);
      ffma2(acc[3][0], pa3, bv0.x); ffma2(acc[3][1], pa3, bv0.y);
      ffma2(acc[3][2], pa3, bv1.x); ffma2(acc[3][3], pa3, bv1.y);
    }
    if (it + 1 < NT) {
      const int nb = buf ^ 1;
      As[nb][akq + 0][am] = a0.x; As[nb][akq + 1][am] = a0.y;
      As[nb][akq + 2][am] = a0.z; As[nb][akq + 3][am] = a0.w;
      *(float4*)&Bs[nb][bkr][bcq]      = b0;
      *(float4*)&Bs[nb][bkr][bcq + 4]  = b1;
      *(float4*)&Bs[nb][bkr][bcq + 8]  = b2;
      *(float4*)&Bs[nb][bkr][bcq + 12] = b3;
    }
    __syncthreads();
  }

  float* yp = Yp + (size_t)z * (ROWS * DD) + (size_t)(bm0 + r0) * DD + c0;
  #pragma unroll
  for (int i = 0; i < 4; i++) {
    float2 u0 = unpack2(acc[i][0]), u1 = unpack2(acc[i][1]);
    float2 u2 = unpack2(acc[i][2]), u3 = unpack2(acc[i][3]);
    *(float4*)(yp + (size_t)i * DD)     = make_float4(u0.x, u0.y, u1.x, u1.y);
    *(float4*)(yp + (size_t)i * DD + 4) = make_float4(u2.x, u2.y, u3.x, u3.y);
  }
}

// ================ combine + bias (+relu|+res) + LayerNorm + write tf32 X fragments ================
template <int RELU, int RES, int TWO>
__global__ void __launch_bounds__(256) k_combln(
    const float* __restrict__ p0, const float* __restrict__ p1,
    const float* __restrict__ bias, const float* __restrict__ res,
    const float* __restrict__ g, const float* __restrict__ beta,
    float* __restrict__ Y, float* __restrict__ Xf) {
  const int row = blockIdx.x * 8 + (threadIdx.x >> 5);
  const int lane = threadIdx.x & 31;
  const int c0 = lane * 4;
  const size_t off = (size_t)row * DD + c0;

  float4 v = *(const float4*)&p0[off];
  if (TWO) {
    float4 w = *(const float4*)&p1[off];
    v.x += w.x; v.y += w.y; v.z += w.z; v.w += w.w;
  }
  float4 bv = *(const float4*)&bias[c0];
  v.x += bv.x; v.y += bv.y; v.z += bv.z; v.w += bv.w;
  if (RELU) {
    v.x = fmaxf(v.x, 0.f); v.y = fmaxf(v.y, 0.f);
    v.z = fmaxf(v.z, 0.f); v.w = fmaxf(v.w, 0.f);
  }
  if (RES) {
    float4 r = *(const float4*)&res[off];
    v.x += r.x; v.y += r.y; v.z += r.z; v.w += r.w;
  }
  float s  = v.x + v.y + v.z + v.w;
  float s2 = v.x * v.x + v.y * v.y + v.z * v.z + v.w * v.w;
  #pragma unroll
  for (int o = 16; o; o >>= 1) {
    s  += __shfl_xor_sync(0xffffffffu, s,  o);
    s2 += __shfl_xor_sync(0xffffffffu, s2, o);
  }
  float mu = s * (1.f / 128.f);
  float var = s2 * (1.f / 128.f) - mu * mu;
  float rstd = rsqrtf(var + EPSF);
  float4 gv = *(const float4*)&g[c0];
  float4 ev = *(const float4*)&beta[c0];
  float o0 = (v.x - mu) * rstd * gv.x + ev.x;
  float o1 = (v.y - mu) * rstd * gv.y + ev.y;
  float o2 = (v.z - mu) * rstd * gv.z + ev.z;
  float o3 = (v.w - mu) * rstd * gv.w + ev.w;
  *(float4*)&Y[off] = make_float4(o0, o1, o2, o3);

  // write tf32 hi/lo fragments: Xf[ks][rt][lane_f][8]
  const int rt = row >> 4, r = row & 15;
  float ov[4] = {o0, o1, o2, o3};
  #pragma unroll
  for (int j = 0; j < 4; j++) {
    const int k = c0 + j;
    const int ks = k >> 3, kk = k & 7;
    const int lane_f = ((r & 7) << 2) | (kk & 3);
    const int reg = (r >> 3) | ((kk >> 2) << 1);
    const size_t idx = (size_t)((ks << 8) | rt) * 256 + lane_f * 8 + reg;
    u32 hi = f2tf(ov[j]);
    float hf = __uint_as_float(hi);
    Xf[idx]     = hf;
    Xf[idx + 4] = __uint_as_float(f2tf(ov[j] - hf));
  }
}

// ================ attention: branch-free split-K partials, 2 queries per thread ================
__global__ void __launch_bounds__(128) k_attn_part(const float* __restrict__ qkv,
                                                   float* __restrict__ po,
                                                   float* __restrict__ pl) {
  const int split = blockIdx.x, h = blockIdx.y, b = blockIdx.z;
  const int t = threadIdx.x;  // 128
  const int q0 = t, q1 = t + 128;
  __shared__ float Ks[64][DHH], Vs[64][DHH];
  const float* base = qkv + (size_t)b * NN * (3 * DD);
  const int hoff = h * DHH;
  const int kbase = split * 64;

  for (int c = t; c < 64 * DHH / 4; c += 128) {
    int r = c >> 3, d4 = (c & 7) << 2;
    *(float4*)&Ks[r][d4] = *(const float4*)&base[(size_t)(kbase + r) * (3 * DD) + DD     + hoff + d4];
    *(float4*)&Vs[r][d4] = *(const float4*)&base[(size_t)(kbase + r) * (3 * DD) + 2 * DD + hoff + d4];
  }
  u64 qp0[16], qp1[16];
  {
    const ulonglong2* qa = (const ulonglong2*)(base + (size_t)q0 * (3 * DD) + hoff);
    const ulonglong2* qb = (const ulonglong2*)(base + (size_t)q1 * (3 * DD) + hoff);
    #pragma unroll
    for (int i = 0; i < 8; i++) {
      ulonglong2 u = qa[i]; qp0[2*i] = u.x; qp0[2*i+1] = u.y;
      ulonglong2 v = qb[i]; qp1[2*i] = v.x; qp1[2*i+1] = v.y;
    }
  }
  __syncthreads();

  float l0 = 0.f, l1 = 0.f;
  u64 op0[16], op1[16];
  #pragma unroll
  for (int i = 0; i < 16; i++) { op0[i] = 0ull; op1[i] = 0ull; }
  const float scale = 0.17677669529663687f;

  for (int k = 0; k < 64; k++) {
    const ulonglong2* kr = (const ulonglong2*)&Ks[k][0];
    u64 sa0 = 0, sa1 = 0, sa2 = 0, sa3 = 0;
    u64 sb0 = 0, sb1 = 0, sb2 = 0, sb3 = 0;
    #pragma unroll
    for (int i = 0; i < 4; i++) {
      ulonglong2 ka = kr[2*i], kb = kr[2*i+1];
      ffma2(sa0, qp0[4*i],     ka.x);
      ffma2(sa1, qp0[4*i + 1], ka.y);
      ffma2(sa2, qp0[4*i + 2], kb.x);
      ffma2(sa3, qp0[4*i + 3], kb.y);
      ffma2(sb0, qp1[4*i],     ka.x);
      ffma2(sb1, qp1[4*i + 1], ka.y);
      ffma2(sb2, qp1[4*i + 2], kb.x);
      ffma2(sb3, qp1[4*i + 3], kb.y);
    }
    u64 ra = add2(add2(sa0, sa1), add2(sa2, sa3));
    u64 rb = add2(add2(sb0, sb1), add2(sb2, sb3));
    float2 ua = unpack2(ra), ub = unpack2(rb);
    float p0 = __expf((ua.x + ua.y) * scale);
    float p1 = __expf((ub.x + ub.y) * scale);
    l0 += p0;
    l1 += p1;
    u64 pp0 = pack2(p0, p0), pp1 = pack2(p1, p1);
    const ulonglong2* vr = (const ulonglong2*)&Vs[k][0];
    #pragma unroll
    for (int i = 0; i < 8; i++) {
      ulonglong2 vv = vr[i];
      ffma2(op0[2*i],     pp0, vv.x);
      ffma2(op0[2*i + 1], pp0, vv.y);
      ffma2(op1[2*i],     pp1, vv.x);
      ffma2(op1[2*i + 1], pp1, vv.y);
    }
  }

  const int bh = (b * HH + h) * NN;
  {
    const int bhq = bh + q0;
    float* pop = po + ((size_t)split * BHQ + bhq) * 32;
    #pragma unroll
    for (int i = 0; i < 8; i++) {
      float2 a = unpack2(op0[2*i]), c = unpack2(op0[2*i + 1]);
      *(float4*)&pop[4*i] = make_float4(a.x, a.y, c.x, c.y);
    }
    pl[(size_t)split * BHQ + bhq] = l0;
  }
  {
    const int bhq = bh + q1;
    float* pop = po + ((size_t)split * BHQ + bhq) * 32;
    #pragma unroll
    for (int i = 0; i < 8; i++) {
      float2 a = unpack2(op1[2*i]), c = unpack2(op1[2*i + 1]);
      *(float4*)&pop[4*i] = make_float4(a.x, a.y, c.x, c.y);
    }
    pl[(size_t)split * BHQ + bhq] = l1;
  }
}

// ================ pair kernel: 64i x 64j per block, 4x4 pairs per thread ================
#define SP 132
__global__ void __launch_bounds__(256) k_pair(const float* __restrict__ w2,
                                              const float* __restrict__ b2,
                                              float* __restrict__ out) {
  extern __shared__ float sm[];
  float* smA = sm;
  float* smB = sm + 64 * SP;
  float* smw = sm + 128 * SP;
  const int b  = blockIdx.z;
  const int i0 = blockIdx.x * 64;
  const int j0 = blockIdx.y * 64;
  const int t  = threadIdx.x;
  const int jx = t & 15, iy = t >> 4;

  {
    const float* Ab = g_A  + ((size_t)(b * NN + i0)) * DD;
    const float* Bb = g_Bm + ((size_t)(b * NN + j0)) * DD;
    for (int idx = t; idx < 64 * 32; idx += 256) {
      int r = idx >> 5, dq = (idx & 31) << 2;
      *(float4*)&smA[r * SP + dq] = *(const float4*)&Ab[(size_t)r * DD + dq];
      *(float4*)&smB[r * SP + dq] = *(const float4*)&Bb[(size_t)r * DD + dq];
    }
    if (t < 32) *(float4*)&smw[t * 4] = *(const float4*)&w2[t * 4];
  }
  __syncthreads();

  const int ibl = iy * 4;
  u64 acc[4][4];
  #pragma unroll
  for (int ii = 0; ii < 4; ii++)
    #pragma unroll
    for (int jj = 0; jj < 4; jj++) acc[ii][jj] = 0ull;

  for (int d = 0; d < DD; d += 4) {
    ulonglong2 wv = *(const ulonglong2*)&smw[d];
    ulonglong2 av[4], bv[4];
    #pragma unroll
    for (int ii = 0; ii < 4; ii++) av[ii] = *(const ulonglong2*)&smA[(ibl + ii) * SP + d];
    #pragma unroll
    for (int jj = 0; jj < 4; jj++) bv[jj] = *(const ulonglong2*)&smB[(jx + 16 * jj) * SP + d];
    #pragma unroll
    for (int ii = 0; ii < 4; ii++) {
      #pragma unroll
      for (int jj = 0; jj < 4; jj++) {
        u64 s0 = relu2(add2(av[ii].x, bv[jj].x));
        ffma2(acc[ii][jj], s0, wv.x);
        u64 s1 = relu2(add2(av[ii].y, bv[jj].y));
        ffma2(acc[ii][jj], s1, wv.y);
      }
    }
  }

  const float b2v = b2[0];
  float* outb = out + (size_t)b * PP;
  #pragma unroll
  for (int ii = 0; ii < 4; ii++) {
    const int i = i0 + ibl + ii;
    #pragma unroll
    for (int jj = 0; jj < 4; jj++) {
      const int j = j0 + jx + 16 * jj;
      if (j != i) {
        float2 u = unpack2(acc[ii][jj]);
        outb[i * (NN - 1) + j - (j > i ? 1 : 0)] = u.x + u.y + b2v;
      }
    }
  }
}

// ================ host ================
extern "C" void kernel_launch(void* const* d_in, const int* in_sizes, int n_in,
                              void* d_out, int out_size) {
  const float* agents   = (const float*)d_in[0];
  const float* enc_w    = (const float*)d_in[1];
  const float* enc_b    = (const float*)d_in[2];
  const float* enc_g    = (const float*)d_in[3];
  const float* enc_beta = (const float*)d_in[4];
  const float* qkv_w    = (const float*)d_in[5];
  const float* qkv_b    = (const float*)d_in[6];
  const float* attn_ow  = (const float*)d_in[7];
  const float* attn_ob  = (const float*)d_in[8];
  const float* ln1_g    = (const float*)d_in[9];
  const float* ln1_b    = (const float*)d_in[10];
  const float* ffn_w1   = (const float*)d_in[11];
  const float* ffn_b1   = (const float*)d_in[12];
  const float* ffn_w2   = (const float*)d_in[13];
  const float* ffn_b2   = (const float*)d_in[14];
  const float* ln2_g    = (const float*)d_in[15];
  const float* ln2_b    = (const float*)d_in[16];
  const float* rel_w1   = (const float*)d_in[17];
  const float* rel_b1   = (const float*)d_in[18];
  const float* rel_w2   = (const float*)d_in[19];
  const float* rel_b2   = (const float*)d_in[20];
  float* out = (float*)d_out;

  float *px, *pqkv, *pffn, *pA, *pBm, *pWf, *pXf;
  cudaGetSymbolAddress((void**)&px,    g_x);
  cudaGetSymbolAddress((void**)&pqkv,  g_qkv);
  cudaGetSymbolAddress((void**)&pffn,  g_ffn);
  cudaGetSymbolAddress((void**)&pA,    g_A);
  cudaGetSymbolAddress((void**)&pBm,   g_Bm);
  cudaGetSymbolAddress((void**)&pWf,   g_Wf);
  cudaGetSymbolAddress((void**)&pXf,   g_Xf);
  float* ppart = pqkv;             // split-K partials
  float* ppo   = pffn;             // attention partial outputs
  float* ppl   = pA;               // attention partial l sums

  const int pair_smem = (128 * SP + 128) * sizeof(float);
  cudaFuncSetAttribute(k_pair, cudaFuncAttributeMaxDynamicSharedMemorySize, pair_smem);

  // weight fragment split (all weights, one launch)
  k_wsplit<<<512, 256>>>(qkv_w, ffn_w1, rel_w1, pWf);

  // encoder: relu(agents @ enc_w + b) -> LN (writes x and Xf)
  k_gemmP<0><<<dim3(ROWS / 32, 1, 1), 128>>>(agents, nullptr, nullptr, FF, FF,
                                             enc_w, ppart);
  k_combln<1, 0, 0><<<ROWS / 8, 256>>>(ppart, nullptr, enc_b, nullptr,
                                       enc_g, enc_beta, px, pXf);

  for (int l = 0; l < LL; l++) {
    // qkv via tf32 MMA
    k_tfmm<0><<<dim3(ROWS / 64, 6), 128>>>(pXf, pWf + WF_QKV + (size_t)l * WF_QKV_L,
                                           3 * DD, 48, qkv_b + (size_t)l * 3 * DD,
                                           pqkv, nullptr);
    // attention partials
    k_attn_part<<<dim3(SPLITS, HH, BB), 128>>>(pqkv, ppo, ppl);
    // proj (attention combine fused), split-K x2
    k_gemmP<1><<<dim3(ROWS / 32, 1, 2), 128>>>(nullptr, ppo, ppl, DD, DD / 2,
                                               attn_ow + (size_t)l * DD * DD, ppart);
    k_combln<0, 1, 1><<<ROWS / 8, 256>>>(ppart, ppart + (size_t)ROWS * DD,
                                         attn_ob + (size_t)l * DD, px,
                                         ln1_g + (size_t)l * DD, ln1_b + (size_t)l * DD,
                                         px, pXf);
    // ffn1 via tf32 MMA
    k_tfmm<1><<<dim3(ROWS / 64, 8), 128>>>(pXf, pWf + WF_FFN1 + (size_t)l * WF_FFN1_L,
                                           DFF_, 64, ffn_b1 + (size_t)l * DFF_,
                                           pffn, nullptr);
    // ffn2 split-K x2
    k_gemmP<0><<<dim3(ROWS / 32, 1, 2), 128>>>(pffn, nullptr, nullptr, DFF_, DFF_ / 2,
                                               ffn_w2 + (size_t)l * DFF_ * DD, ppart);
    k_combln<0, 1, 1><<<ROWS / 8, 256>>>(ppart, ppart + (size_t)ROWS * DD,
                                         ffn_b2 + (size_t)l * DD, px,
                                         ln2_g + (size_t)l * DD, ln2_b + (size_t)l * DD,
                                         px, pXf);
  }

  // pair precompute via tf32 MMA (dual output)
  k_tfmm<5><<<dim3(ROWS / 64, 4), 128>>>(pXf, pWf + WF_REL, DD, 32, rel_b1, pA, pBm);

  k_pair<<<dim3(NN / 64, NN / 64, BB), 256, pair_smem>>>(rel_w2, rel_b2, out);
}

// round 13
// speedup vs baseline: 1.2257x; 1.1181x over previous
#include <cuda_runtime.h>

#define BB 16
#define NN 256
#define FF 64
#define DD 128
#define HH 4
#define DHH 32
#define DFF_ 512
#define LL 2
#define ROWS (BB*NN)     // 4096
#define PP (NN*(NN-1))   // 65280
#define EPSF 1e-5f
#define SPLITS 4
#define BHQ (BB*HH*NN)   // 16384

// Wf segment offsets (floats)
#define WF_QKV   0
#define WF_QKV_L (16*48*128)          // 98304 per layer
#define WF_FFN1  (2*WF_QKV_L)         // 196608
#define WF_FFN1_L (16*64*128)         // 131072 per layer
#define WF_REL   (WF_FFN1 + 2*WF_FFN1_L)  // 458752
#define WF_FFN2  (WF_REL + 16*32*128)     // 524288
#define WF_FFN2_L (64*16*128)             // 131072 per layer
#define WF_TOTAL (WF_FFN2 + 2*WF_FFN2_L)  // 786432

// ---------------- scratch ----------------
__device__ float g_x[ROWS*DD];
__device__ float g_qkv[ROWS*3*DD];    // qkv; reused for GEMM split-K partials
__device__ float g_ffn[ROWS*DFF_];    // attention po scratch
__device__ float g_A[ROWS*DD];        // pairpre A; also attention l scratch
__device__ float g_Bm[ROWS*DD];
__device__ float g_Wf[WF_TOTAL];      // tf32 hi/lo weight fragments
__device__ float g_Xf[16*256*32*8];   // tf32 hi/lo X fragments  [ks][rt][lane][8]
__device__ float g_Xf2[64*256*32*8];  // tf32 hi/lo ffn1-out fragments (K=512)

typedef unsigned long long u64;
typedef unsigned int u32;

__device__ __forceinline__ u64 pack2(float x, float y) {
  u64 r; asm("mov.b64 %0, {%1, %2};" : "=l"(r) : "f"(x), "f"(y)); return r;
}
__device__ __forceinline__ float2 unpack2(u64 v) {
  float2 r; asm("mov.b64 {%0, %1}, %2;" : "=f"(r.x), "=f"(r.y) : "l"(v)); return r;
}
__device__ __forceinline__ void ffma2(u64 &d, u64 a, u64 b) {
  asm("fma.rn.f32x2 %0, %1, %2, %0;" : "+l"(d) : "l"(a), "l"(b));
}
__device__ __forceinline__ u64 add2(u64 a, u64 b) {
  u64 o; asm("add.rn.f32x2 %0, %1, %2;" : "=l"(o) : "l"(a), "l"(b)); return o;
}
__device__ __forceinline__ u64 relu2(u64 v) {
  float2 f = unpack2(v);
  return pack2(fmaxf(f.x, 0.f), fmaxf(f.y, 0.f));
}
__device__ __forceinline__ u32 f2tf(float x) {
  u32 r; asm("cvt.rna.tf32.f32 %0, %1;" : "=r"(r) : "f"(x)); return r;
}
__device__ __forceinline__ void mma8(float& c0, float& c1, float& c2, float& c3,
                                     u32 a0, u32 a1, u32 a2, u32 a3, u32 b0, u32 b1) {
  asm volatile(
      "mma.sync.aligned.m16n8k8.row.col.f32.tf32.tf32.f32 "
      "{%0,%1,%2,%3}, {%4,%5,%6,%7}, {%8,%9}, {%0,%1,%2,%3};"
      : "+f"(c0), "+f"(c1), "+f"(c2), "+f"(c3)
      : "r"(a0), "r"(a1), "r"(a2), "r"(a3), "r"(b0), "r"(b1));
}

// ================ weight split: fp32 -> tf32 hi/lo fragments ================
// Segments: qkv (Z=2,K=128,N=384), ffn1 (Z=2,K=128,N=512), rel (K=128,N=256), ffn2 (Z=2,K=512,N=128)
__global__ void __launch_bounds__(256) k_wsplit(const float* __restrict__ qkv_w,
                                                const float* __restrict__ ffn1_w,
                                                const float* __restrict__ rel_w1,
                                                const float* __restrict__ ffn2_w,
                                                float* __restrict__ Wf) {
  const int tid = blockIdx.x * 256 + threadIdx.x;  // 196608 total
  const float* src;
  int NT, N, KS, local, dstoff, rel = 0;
  if (tid < 49152)        { src = qkv_w;  NT = 48; N = 384; KS = 16; local = tid;          dstoff = WF_QKV; }
  else if (tid < 114688)  { src = ffn1_w; NT = 64; N = 512; KS = 16; local = tid - 49152;  dstoff = WF_FFN1; }
  else if (tid < 131072)  { src = rel_w1; NT = 32; N = 256; KS = 16; local = tid - 114688; dstoff = WF_REL; rel = 1; }
  else                    { src = ffn2_w; NT = 16; N = 128; KS = 64; local = tid - 131072; dstoff = WF_FFN2; }
  const int lane = local & 31;
  int u = local >> 5;
  const int nt = u % NT; u /= NT;
  const int ks = u % KS;
  const int z  = u / KS;
  const int n = nt * 8 + (lane >> 2);
  const int KK = KS * 8;
  float w[4];
  #pragma unroll
  for (int reg = 0; reg < 2; reg++) {
    const int kk = (lane & 3) + 4 * reg;
    const int k = ks * 8 + kk;
    float v;
    if (rel) v = src[(size_t)((n < 128) ? k : k + 128) * 128 + (n & 127)];
    else     v = src[(size_t)(z * KK + k) * N + n];
    u32 hi = f2tf(v);
    float hf = __uint_as_float(hi);
    u32 lo = f2tf(v - hf);
    w[reg]     = hf;
    w[reg + 2] = __uint_as_float(lo);
  }
  *(float4*)&Wf[(size_t)dstoff + (size_t)(((z * KS + ks) * NT + nt) * 32 + lane) * 4] =
      make_float4(w[0], w[1], w[2], w[3]);
}

// ================ tf32 MMA GEMM: smem-staged W, double-buffered, prefetched ================
// Block: 128 threads (4 warps). Warp tile 16x64.
// EPI: 0 = +bias ; 1 = +bias,relu ; 2 = +bias,relu,write Xf2 fragments (ffn1) ;
//      5 = pairpre dual ; 6 = split-K partial (blockIdx.z selects ks half, no bias)
template <int EPI>
__global__ void __launch_bounds__(128) k_tfmm(
    const float* __restrict__ Xf, const float* __restrict__ Wf,
    int NOUT, int NTILES, int KS,
    const float* __restrict__ bias,
    float* __restrict__ Y, float* __restrict__ Y2) {
  __shared__ float Ws[2][1024];      // 8 nt tiles x 128 floats, double buffered
  const int t = threadIdx.x;
  const int w = t >> 5, lane = t & 31;
  const int gid = lane >> 2, tig = lane & 3;
  const int rt = blockIdx.x * 4 + w;
  const int ntg0 = blockIdx.y * 8;

  if (EPI == 6) {
    const size_t z = blockIdx.z;
    Wf += z * (size_t)KS * NTILES * 128;
    Xf += z * (size_t)KS * 65536;
    Y  += z * (size_t)ROWS * 128;
  }

  float acc[8][4];
  #pragma unroll
  for (int nt = 0; nt < 8; nt++) {
    float b0 = 0.f, b1 = 0.f;
    if (EPI != 6 && (EPI != 5 || blockIdx.y < 2)) {
      const int c = (ntg0 + nt) * 8 + tig * 2;
      b0 = bias[c]; b1 = bias[c + 1];
    }
    acc[nt][0] = b0; acc[nt][1] = b1; acc[nt][2] = b0; acc[nt][3] = b1;
  }

  const float4* wgp = (const float4*)(Wf + (size_t)ntg0 * 128);
  const uint4*  xfp = (const uint4*)(Xf + (size_t)(rt * 32 + lane) * 8);

  // Preload ks = 0
  float4 cw0 = wgp[t], cw1 = wgp[t + 128];
  uint4 ah = xfp[0], al = xfp[1];
  *(float4*)&Ws[0][t * 4]         = cw0;
  *(float4*)&Ws[0][(t + 128) * 4] = cw1;
  __syncthreads();

  int buf = 0;
  for (int ks = 0; ks < KS; ks++) {
    float4 nw0, nw1;
    uint4 nah, nal;
    if (ks + 1 < KS) {
      const size_t wo = (size_t)(ks + 1) * NTILES * 32;
      nw0 = wgp[wo + t];
      nw1 = wgp[wo + t + 128];
      nah = xfp[(size_t)(ks + 1) * 16384];
      nal = xfp[(size_t)(ks + 1) * 16384 + 1];
    }
    #pragma unroll
    for (int nt = 0; nt < 8; nt++) {
      uint4 b = *(const uint4*)&Ws[buf][nt * 128 + lane * 4];
      mma8(acc[nt][0], acc[nt][1], acc[nt][2], acc[nt][3],
           ah.x, ah.y, ah.z, ah.w, b.x, b.y);
      mma8(acc[nt][0], acc[nt][1], acc[nt][2], acc[nt][3],
           ah.x, ah.y, ah.z, ah.w, b.z, b.w);
      mma8(acc[nt][0], acc[nt][1], acc[nt][2], acc[nt][3],
           al.x, al.y, al.z, al.w, b.x, b.y);
    }
    if (ks + 1 < KS) {
      const int nb = buf ^ 1;
      *(float4*)&Ws[nb][t * 4]         = nw0;
      *(float4*)&Ws[nb][(t + 128) * 4] = nw1;
      ah = nah; al = nal;
      __syncthreads();
      buf = nb;
    }
  }

  const int row0 = rt * 16 + gid;
  #pragma unroll
  for (int nt = 0; nt < 8; nt++) {
    int colg = (ntg0 + nt) * 8 + tig * 2;
    float f0 = acc[nt][0], f1 = acc[nt][1], f2 = acc[nt][2], f3 = acc[nt][3];
    if (EPI == 1 || EPI == 2) {
      f0 = fmaxf(f0, 0.f); f1 = fmaxf(f1, 0.f);
      f2 = fmaxf(f2, 0.f); f3 = fmaxf(f3, 0.f);
    }
    if (EPI == 2) {
      // write tf32 hi/lo fragments for the K=512 GEMM: ksO = ntg0+nt (8 cols per tile)
      const int ksO = ntg0 + nt;
      const int kk0 = tig * 2;
      const int lane_f = (gid << 2) | (kk0 & 3);          // for col kk0; col kk0+1 -> lane_f+1
      const int reg0 = ((kk0 >> 2) << 1);                 // rows row0 -> reg0, row0+8 -> reg0+1
      float* base = Y + ((size_t)(ksO * 256 + rt) * 32 + lane_f) * 8 + reg0;
      u32 h0 = f2tf(f0), h2 = f2tf(f2);
      *(float2*)base       = make_float2(__uint_as_float(h0), __uint_as_float(h2));
      *(float2*)(base + 4) = make_float2(f0 - __uint_as_float(h0), f2 - __uint_as_float(h2));
      u32 h1 = f2tf(f1), h3 = f2tf(f3);
      *(float2*)(base + 8)  = make_float2(__uint_as_float(h1), __uint_as_float(h3));
      *(float2*)(base + 12) = make_float2(f1 - __uint_as_float(h1), f3 - __uint_as_float(h3));
    } else if (EPI == 5) {
      float* Yo = (blockIdx.y < 2) ? Y : Y2;
      const int c = colg & 127;
      *(float2*)&Yo[(size_t)row0 * 128 + c]       = make_float2(f0, f1);
      *(float2*)&Yo[(size_t)(row0 + 8) * 128 + c] = make_float2(f2, f3);
    } else {
      *(float2*)&Y[(size_t)row0 * NOUT + colg]       = make_float2(f0, f1);
      *(float2*)&Y[(size_t)(row0 + 8) * NOUT + colg] = make_float2(f2, f3);
    }
  }
}

// ================ GEMM P: partial split-K, BM=32, BN=128, BK=16, 128 threads, 4x8 tile ================
template <int ATTN>
__global__ void __launch_bounds__(128) k_gemmP(
    const float* __restrict__ X,
    const float* __restrict__ po, const float* __restrict__ pl,
    int KK, int KH,
    const float* __restrict__ W,
    float* __restrict__ Yp) {
  __shared__ float As[2][16][32];
  __shared__ float Bs[2][16][128];
  const int t  = threadIdx.x;
  const int tx = t & 15, ty = t >> 4;
  const int bm0 = blockIdx.x * 32;
  const int z   = blockIdx.z;
  const int r0 = ty * 4, c0 = tx * 8;
  const int am = t >> 2,  akq = (t & 3) * 4;
  const int bkr = t >> 3, bcq = (t & 7) * 16;

  const int row = bm0 + am;
  const int kb  = z * KH + akq;

  int bq_b = 0, bq_q = 0;
  if (ATTN) { bq_b = row >> 8; bq_q = row & 255; }

  u64 acc[4][4];
  #pragma unroll
  for (int i = 0; i < 4; i++) { acc[i][0]=0; acc[i][1]=0; acc[i][2]=0; acc[i][3]=0; }

  const float* Xp = X + (size_t)row * KK + kb;
  const float* Wp = W + (size_t)(z * KH + bkr) * 128 + bcq;
  const int NT = KH >> 4;

  auto loadA = [&](int it) -> float4 {
    if (!ATTN) {
      return *(const float4*)(Xp + it * 16);
    } else {
      const int kk = kb + it * 16;
      const int h = kk >> 5, d4 = kk & 31;
      const int bhq = (bq_b * HH + h) * NN + bq_q;
      float lsum = pl[bhq] + pl[BHQ + bhq] + pl[2 * BHQ + bhq] + pl[3 * BHQ + bhq];
      float inv = 1.f / lsum;
      float4 p0 = *(const float4*)&po[((size_t)bhq) * 32 + d4];
      float4 p1 = *(const float4*)&po[((size_t)BHQ + bhq) * 32 + d4];
      float4 p2 = *(const float4*)&po[((size_t)2 * BHQ + bhq) * 32 + d4];
      float4 p3 = *(const float4*)&po[((size_t)3 * BHQ + bhq) * 32 + d4];
      return make_float4((p0.x + p1.x + p2.x + p3.x) * inv,
                         (p0.y + p1.y + p2.y + p3.y) * inv,
                         (p0.z + p1.z + p2.z + p3.z) * inv,
                         (p0.w + p1.w + p2.w + p3.w) * inv);
    }
  };

  float4 a0 = loadA(0);
  float4 b0 = *(const float4*)Wp;
  float4 b1 = *(const float4*)(Wp + 4);
  float4 b2 = *(const float4*)(Wp + 8);
  float4 b3 = *(const float4*)(Wp + 12);
  {
    As[0][akq + 0][am] = a0.x; As[0][akq + 1][am] = a0.y;
    As[0][akq + 2][am] = a0.z; As[0][akq + 3][am] = a0.w;
    *(float4*)&Bs[0][bkr][bcq]      = b0;
    *(float4*)&Bs[0][bkr][bcq + 4]  = b1;
    *(float4*)&Bs[0][bkr][bcq + 8]  = b2;
    *(float4*)&Bs[0][bkr][bcq + 12] = b3;
  }
  __syncthreads();

  for (int it = 0; it < NT; it++) {
    const int buf = it & 1;
    if (it + 1 < NT) {
      a0 = loadA(it + 1);
      const float* wp = Wp + (size_t)(it + 1) * 16 * 128;
      b0 = *(const float4*)wp;        b1 = *(const float4*)(wp + 4);
      b2 = *(const float4*)(wp + 8);  b3 = *(const float4*)(wp + 12);
    }
    #pragma unroll
    for (int k = 0; k < 16; k++) {
      float4 av = *(const float4*)&As[buf][k][r0];
      ulonglong2 bv0 = *(const ulonglong2*)&Bs[buf][k][c0];
      ulonglong2 bv1 = *(const ulonglong2*)&Bs[buf][k][c0 + 4];
      u64 pa0 = pack2(av.x, av.x);
      u64 pa1 = pack2(av.y, av.y);
      u64 pa2 = pack2(av.z, av.z);
      u64 pa3 = pack2(av.w, av.w);
      ffma2(acc[0][0], pa0, bv0.x); ffma2(acc[0][1], pa0, bv0.y);
      ffma2(acc[0][2], pa0, bv1.x); ffma2(acc[0][3], pa0, bv1.y);
      ffma2(acc[1][0], pa1, bv0.x); ffma2(acc[1][1], pa1, bv0.y);
      ffma2(acc[1][2], pa1, bv1.x); ffma2(acc[1][3], pa1, bv1.y);
      ffma2(acc[2][0], pa2, bv0.x); ffma2(acc[2][1], pa2, bv0.y);
      ffma2(acc[2][2], pa2, bv1.x); ffma2(acc[2][3], pa2, bv1.y);
      ffma2(acc[3][0], pa3, bv0.x); ffma2(acc[3][1], pa3, bv0.y);
      ffma2(acc[3][2], pa3, bv1.x); ffma2(acc[3][3], pa3, bv1.y);
    }
    if (it + 1 < NT) {
      const int nb = buf ^ 1;
      As[nb][akq + 0][am] = a0.x; As[nb][akq + 1][am] = a0.y;
      As[nb][akq + 2][am] = a0.z; As[nb][akq + 3][am] = a0.w;
      *(float4*)&Bs[nb][bkr][bcq]      = b0;
      *(float4*)&Bs[nb][bkr][bcq + 4]  = b1;
      *(float4*)&Bs[nb][bkr][bcq + 8]  = b2;
      *(float4*)&Bs[nb][bkr][bcq + 12] = b3;
    }
    __syncthreads();
  }

  float* yp = Yp + (size_t)z * (ROWS * DD) + (size_t)(bm0 + r0) * DD + c0;
  #pragma unroll
  for (int i = 0; i < 4; i++) {
    float2 u0 = unpack2(acc[i][0]), u1 = unpack2(acc[i][1]);
    float2 u2 = unpack2(acc[i][2]), u3 = unpack2(acc[i][3]);
    *(float4*)(yp + (size_t)i * DD)     = make_float4(u0.x, u0.y, u1.x, u1.y);
    *(float4*)(yp + (size_t)i * DD + 4) = make_float4(u2.x, u2.y, u3.x, u3.y);
  }
}

// ================ combine + bias (+relu|+res) + LayerNorm + write tf32 X fragments ================
template <int RELU, int RES, int TWO>
__global__ void __launch_bounds__(256) k_combln(
    const float* __restrict__ p0, const float* __restrict__ p1,
    const float* __restrict__ bias, const float* __restrict__ res,
    const float* __restrict__ g, const float* __restrict__ beta,
    float* __restrict__ Y, float* __restrict__ Xf) {
  const int row = blockIdx.x * 8 + (threadIdx.x >> 5);
  const int lane = threadIdx.x & 31;
  const int c0 = lane * 4;
  const size_t off = (size_t)row * DD + c0;

  float4 v = *(const float4*)&p0[off];
  if (TWO) {
    float4 w = *(const float4*)&p1[off];
    v.x += w.x; v.y += w.y; v.z += w.z; v.w += w.w;
  }
  float4 bv = *(const float4*)&bias[c0];
  v.x += bv.x; v.y += bv.y; v.z += bv.z; v.w += bv.w;
  if (RELU) {
    v.x = fmaxf(v.x, 0.f); v.y = fmaxf(v.y, 0.f);
    v.z = fmaxf(v.z, 0.f); v.w = fmaxf(v.w, 0.f);
  }
  if (RES) {
    float4 r = *(const float4*)&res[off];
    v.x += r.x; v.y += r.y; v.z += r.z; v.w += r.w;
  }
  float s  = v.x + v.y + v.z + v.w;
  float s2 = v.x * v.x + v.y * v.y + v.z * v.z + v.w * v.w;
  #pragma unroll
  for (int o = 16; o; o >>= 1) {
    s  += __shfl_xor_sync(0xffffffffu, s,  o);
    s2 += __shfl_xor_sync(0xffffffffu, s2, o);
  }
  float mu = s * (1.f / 128.f);
  float var = s2 * (1.f / 128.f) - mu * mu;
  float rstd = rsqrtf(var + EPSF);
  float4 gv = *(const float4*)&g[c0];
  float4 ev = *(const float4*)&beta[c0];
  float o0 = (v.x - mu) * rstd * gv.x + ev.x;
  float o1 = (v.y - mu) * rstd * gv.y + ev.y;
  float o2 = (v.z - mu) * rstd * gv.z + ev.z;
  float o3 = (v.w - mu) * rstd * gv.w + ev.w;
  *(float4*)&Y[off] = make_float4(o0, o1, o2, o3);

  // write tf32 hi/lo fragments: Xf[ks][rt][lane_f][8]
  const int rt = row >> 4, r = row & 15;
  float ov[4] = {o0, o1, o2, o3};
  #pragma unroll
  for (int j = 0; j < 4; j++) {
    const int k = c0 + j;
    const int ks = k >> 3, kk = k & 7;
    const int lane_f = ((r & 7) << 2) | (kk & 3);
    const int reg = (r >> 3) | ((kk >> 2) << 1);
    const size_t idx = (size_t)((ks << 8) | rt) * 256 + lane_f * 8 + reg;
    u32 hi = f2tf(ov[j]);
    float hf = __uint_as_float(hi);
    Xf[idx]     = hf;
    Xf[idx + 4] = __uint_as_float(f2tf(ov[j] - hf));
  }
}

// ================ attention: branch-free split-K partials, 2 queries per thread ================
__global__ void __launch_bounds__(128) k_attn_part(const float* __restrict__ qkv,
                                                   float* __restrict__ po,
                                                   float* __restrict__ pl) {
  const int split = blockIdx.x, h = blockIdx.y, b = blockIdx.z;
  const int t = threadIdx.x;  // 128
  const int q0 = t, q1 = t + 128;
  __shared__ float Ks[64][DHH], Vs[64][DHH];
  const float* base = qkv + (size_t)b * NN * (3 * DD);
  const int hoff = h * DHH;
  const int kbase = split * 64;

  for (int c = t; c < 64 * DHH / 4; c += 128) {
    int r = c >> 3, d4 = (c & 7) << 2;
    *(float4*)&Ks[r][d4] = *(const float4*)&base[(size_t)(kbase + r) * (3 * DD) + DD     + hoff + d4];
    *(float4*)&Vs[r][d4] = *(const float4*)&base[(size_t)(kbase + r) * (3 * DD) + 2 * DD + hoff + d4];
  }
  u64 qp0[16], qp1[16];
  {
    const ulonglong2* qa = (const ulonglong2*)(base + (size_t)q0 * (3 * DD) + hoff);
    const ulonglong2* qb = (const ulonglong2*)(base + (size_t)q1 * (3 * DD) + hoff);
    #pragma unroll
    for (int i = 0; i < 8; i++) {
      ulonglong2 u = qa[i]; qp0[2*i] = u.x; qp0[2*i+1] = u.y;
      ulonglong2 v = qb[i]; qp1[2*i] = v.x; qp1[2*i+1] = v.y;
    }
  }
  __syncthreads();

  float l0 = 0.f, l1 = 0.f;
  u64 op0[16], op1[16];
  #pragma unroll
  for (int i = 0; i < 16; i++) { op0[i] = 0ull; op1[i] = 0ull; }
  const float scale = 0.17677669529663687f;

  for (int k = 0; k < 64; k++) {
    const ulonglong2* kr = (const ulonglong2*)&Ks[k][0];
    u64 sa0 = 0, sa1 = 0, sa2 = 0, sa3 = 0;
    u64 sb0 = 0, sb1 = 0, sb2 = 0, sb3 = 0;
    #pragma unroll
    for (int i = 0; i < 4; i++) {
      ulonglong2 ka = kr[2*i], kb = kr[2*i+1];
      ffma2(sa0, qp0[4*i],     ka.x);
      ffma2(sa1, qp0[4*i + 1], ka.y);
      ffma2(sa2, qp0[4*i + 2], kb.x);
      ffma2(sa3, qp0[4*i + 3], kb.y);
      ffma2(sb0, qp1[4*i],     ka.x);
      ffma2(sb1, qp1[4*i + 1], ka.y);
      ffma2(sb2, qp1[4*i + 2], kb.x);
      ffma2(sb3, qp1[4*i + 3], kb.y);
    }
    u64 ra = add2(add2(sa0, sa1), add2(sa2, sa3));
    u64 rb = add2(add2(sb0, sb1), add2(sb2, sb3));
    float2 ua = unpack2(ra), ub = unpack2(rb);
    float p0 = __expf((ua.x + ua.y) * scale);
    float p1 = __expf((ub.x + ub.y) * scale);
    l0 += p0;
    l1 += p1;
    u64 pp0 = pack2(p0, p0), pp1 = pack2(p1, p1);
    const ulonglong2* vr = (const ulonglong2*)&Vs[k][0];
    #pragma unroll
    for (int i = 0; i < 8; i++) {
      ulonglong2 vv = vr[i];
      ffma2(op0[2*i],     pp0, vv.x);
      ffma2(op0[2*i + 1], pp0, vv.y);
      ffma2(op1[2*i],     pp1, vv.x);
      ffma2(op1[2*i + 1], pp1, vv.y);
    }
  }

  const int bh = (b * HH + h) * NN;
  {
    const int bhq = bh + q0;
    float* pop = po + ((size_t)split * BHQ + bhq) * 32;
    #pragma unroll
    for (int i = 0; i < 8; i++) {
      float2 a = unpack2(op0[2*i]), c = unpack2(op0[2*i + 1]);
      *(float4*)&pop[4*i] = make_float4(a.x, a.y, c.x, c.y);
    }
    pl[(size_t)split * BHQ + bhq] = l0;
  }
  {
    const int bhq = bh + q1;
    float* pop = po + ((size_t)split * BHQ + bhq) * 32;
    #pragma unroll
    for (int i = 0; i < 8; i++) {
      float2 a = unpack2(op1[2*i]), c = unpack2(op1[2*i + 1]);
      *(float4*)&pop[4*i] = make_float4(a.x, a.y, c.x, c.y);
    }
    pl[(size_t)split * BHQ + bhq] = l1;
  }
}

// ================ pair kernel: 64i x 64j per block, 4x4 pairs per thread ================
#define SP 132
__global__ void __launch_bounds__(256) k_pair(const float* __restrict__ w2,
                                              const float* __restrict__ b2,
                                              float* __restrict__ out) {
  extern __shared__ float sm[];
  float* smA = sm;
  float* smB = sm + 64 * SP;
  float* smw = sm + 128 * SP;
  const int b  = blockIdx.z;
  const int i0 = blockIdx.x * 64;
  const int j0 = blockIdx.y * 64;
  const int t  = threadIdx.x;
  const int jx = t & 15, iy = t >> 4;

  {
    const float* Ab = g_A  + ((size_t)(b * NN + i0)) * DD;
    const float* Bb = g_Bm + ((size_t)(b * NN + j0)) * DD;
    for (int idx = t; idx < 64 * 32; idx += 256) {
      int r = idx >> 5, dq = (idx & 31) << 2;
      *(float4*)&smA[r * SP + dq] = *(const float4*)&Ab[(size_t)r * DD + dq];
      *(float4*)&smB[r * SP + dq] = *(const float4*)&Bb[(size_t)r * DD + dq];
    }
    if (t < 32) *(float4*)&smw[t * 4] = *(const float4*)&w2[t * 4];
  }
  __syncthreads();

  const int ibl = iy * 4;
  u64 acc[4][4];
  #pragma unroll
  for (int ii = 0; ii < 4; ii++)
    #pragma unroll
    for (int jj = 0; jj < 4; jj++) acc[ii][jj] = 0ull;

  for (int d = 0; d < DD; d += 4) {
    ulonglong2 wv = *(const ulonglong2*)&smw[d];
    ulonglong2 av[4], bv[4];
    #pragma unroll
    for (int ii = 0; ii < 4; ii++) av[ii] = *(const ulonglong2*)&smA[(ibl + ii) * SP + d];
    #pragma unroll
    for (int jj = 0; jj < 4; jj++) bv[jj] = *(const ulonglong2*)&smB[(jx + 16 * jj) * SP + d];
    #pragma unroll
    for (int ii = 0; ii < 4; ii++) {
      #pragma unroll
      for (int jj = 0; jj < 4; jj++) {
        u64 s0 = relu2(add2(av[ii].x, bv[jj].x));
        ffma2(acc[ii][jj], s0, wv.x);
        u64 s1 = relu2(add2(av[ii].y, bv[jj].y));
        ffma2(acc[ii][jj], s1, wv.y);
      }
    }
  }

  const float b2v = b2[0];
  float* outb = out + (size_t)b * PP;
  #pragma unroll
  for (int ii = 0; ii < 4; ii++) {
    const int i = i0 + ibl + ii;
    #pragma unroll
    for (int jj = 0; jj < 4; jj++) {
      const int j = j0 + jx + 16 * jj;
      if (j != i) {
        float2 u = unpack2(acc[ii][jj]);
        outb[i * (NN - 1) + j - (j > i ? 1 : 0)] = u.x + u.y + b2v;
      }
    }
  }
}

// ================ host ================
extern "C" void kernel_launch(void* const* d_in, const int* in_sizes, int n_in,
                              void* d_out, int out_size) {
  const float* agents   = (const float*)d_in[0];
  const float* enc_w    = (const float*)d_in[1];
  const float* enc_b    = (const float*)d_in[2];
  const float* enc_g    = (const float*)d_in[3];
  const float* enc_beta = (const float*)d_in[4];
  const float* qkv_w    = (const float*)d_in[5];
  const float* qkv_b    = (const float*)d_in[6];
  const float* attn_ow  = (const float*)d_in[7];
  const float* attn_ob  = (const float*)d_in[8];
  const float* ln1_g    = (const float*)d_in[9];
  const float* ln1_b    = (const float*)d_in[10];
  const float* ffn_w1   = (const float*)d_in[11];
  const float* ffn_b1   = (const float*)d_in[12];
  const float* ffn_w2   = (const float*)d_in[13];
  const float* ffn_b2   = (const float*)d_in[14];
  const float* ln2_g    = (const float*)d_in[15];
  const float* ln2_b    = (const float*)d_in[16];
  const float* rel_w1   = (const float*)d_in[17];
  const float* rel_b1   = (const float*)d_in[18];
  const float* rel_w2   = (const float*)d_in[19];
  const float* rel_b2   = (const float*)d_in[20];
  float* out = (float*)d_out;

  float *px, *pqkv, *pffn, *pA, *pBm, *pWf, *pXf, *pXf2;
  cudaGetSymbolAddress((void**)&px,    g_x);
  cudaGetSymbolAddress((void**)&pqkv,  g_qkv);
  cudaGetSymbolAddress((void**)&pffn,  g_ffn);
  cudaGetSymbolAddress((void**)&pA,    g_A);
  cudaGetSymbolAddress((void**)&pBm,   g_Bm);
  cudaGetSymbolAddress((void**)&pWf,   g_Wf);
  cudaGetSymbolAddress((void**)&pXf,   g_Xf);
  cudaGetSymbolAddress((void**)&pXf2,  g_Xf2);
  float* ppart = pqkv;             // split-K partials
  float* ppo   = pffn;             // attention partial outputs
  float* ppl   = pA;               // attention partial l sums

  const int pair_smem = (128 * SP + 128) * sizeof(float);
  cudaFuncSetAttribute(k_pair, cudaFuncAttributeMaxDynamicSharedMemorySize, pair_smem);

  // weight fragment split (all weights, one launch)
  k_wsplit<<<768, 256>>>(qkv_w, ffn_w1, rel_w1, ffn_w2, pWf);

  // encoder: relu(agents @ enc_w + b) -> LN (writes x and Xf)
  k_gemmP<0><<<dim3(ROWS / 32, 1, 1), 128>>>(agents, nullptr, nullptr, FF, FF,
                                             enc_w, ppart);
  k_combln<1, 0, 0><<<ROWS / 8, 256>>>(ppart, nullptr, enc_b, nullptr,
                                       enc_g, enc_beta, px, pXf);

  for (int l = 0; l < LL; l++) {
    // qkv via tf32 MMA
    k_tfmm<0><<<dim3(ROWS / 64, 6), 128>>>(pXf, pWf + WF_QKV + (size_t)l * WF_QKV_L,
                                           3 * DD, 48, 16, qkv_b + (size_t)l * 3 * DD,
                                           pqkv, nullptr);
    // attention partials
    k_attn_part<<<dim3(SPLITS, HH, BB), 128>>>(pqkv, ppo, ppl);
    // proj (attention combine fused), split-K x2
    k_gemmP<1><<<dim3(ROWS / 32, 1, 2), 128>>>(nullptr, ppo, ppl, DD, DD / 2,
                                               attn_ow + (size_t)l * DD * DD, ppart);
    k_combln<0, 1, 1><<<ROWS / 8, 256>>>(ppart, ppart + (size_t)ROWS * DD,
                                         attn_ob + (size_t)l * DD, px,
                                         ln1_g + (size_t)l * DD, ln1_b + (size_t)l * DD,
                                         px, pXf);
    // ffn1 via tf32 MMA -> write Xf2 fragments (bias+relu fused)
    k_tfmm<2><<<dim3(ROWS / 64, 8), 128>>>(pXf, pWf + WF_FFN1 + (size_t)l * WF_FFN1_L,
                                           DFF_, 64, 16, ffn_b1 + (size_t)l * DFF_,
                                           pXf2, nullptr);
    // ffn2 via tf32 MMA, split-K z=2 -> partials
    k_tfmm<6><<<dim3(ROWS / 64, 2, 2), 128>>>(pXf2, pWf + WF_FFN2 + (size_t)l * WF_FFN2_L,
                                              DD, 16, 32, nullptr, ppart, nullptr);
    k_combln<0, 1, 1><<<ROWS / 8, 256>>>(ppart, ppart + (size_t)ROWS * DD,
                                         ffn_b2 + (size_t)l * DD, px,
                                         ln2_g + (size_t)l * DD, ln2_b + (size_t)l * DD,
                                         px, pXf);
  }

  // pair precompute via tf32 MMA (dual output)
  k_tfmm<5><<<dim3(ROWS / 64, 4), 128>>>(pXf, pWf + WF_REL, DD, 32, 16, rel_b1, pA, pBm);

  k_pair<<<dim3(NN / 64, NN / 64, BB), 256, pair_smem>>>(rel_w2, rel_b2, out);
}